// round 1
// baseline (speedup 1.0000x reference)
#include <cuda_runtime.h>
#include <math.h>

#define NMAX   12000
#define EMAX   192000
#define F_IN   10
#define C1     32
#define K1     35
#define K2     18
#define EPSF   1e-15f
#define RED_CHUNKS 15

// ---------------- device scratch (static: no runtime allocation) -------------
__device__ float g_dis[NMAX];            // degree accumulator, then D^-1/2
__device__ float g_hn [NMAX * C1];       // dis[i] * (x W1)[i]  (then h1 after k_s)
__device__ float g_acc[NMAX * C1];       // aggregation accumulator
__device__ float g_s  [NMAX * K1];       // softmax cluster assignments
__device__ float g_as [NMAX * K1];       // adj @ s
__device__ float g_out1[K1 * C1];        // s^T h1
__device__ float g_adj1[K1 * K1];        // s^T a_s (raw)

// ---------------- kernels ----------------------------------------------------

__global__ void k_init(int N) {
    int stride = gridDim.x * blockDim.x;
    int t0 = blockIdx.x * blockDim.x + threadIdx.x;
    for (int i = t0; i < N * K1; i += stride) g_as[i] = 0.f;
    for (int i = t0; i < N;      i += stride) g_dis[i] = 1.0f;   // self-loop weight
    for (int i = t0; i < K1*C1;  i += stride) g_out1[i] = 0.f;
    for (int i = t0; i < K1*K1;  i += stride) g_adj1[i] = 0.f;
}

__global__ void k_deg(const int* __restrict__ col, int E) {
    int e = blockIdx.x * blockDim.x + threadIdx.x;
    if (e < E) atomicAdd(&g_dis[col[e]], 1.0f);
}

// dis = deg^-1/2 ; h = x @ W1 ; hn = dis * h ; acc starts as hn (self-loop term)
__global__ void k_h(const float* __restrict__ x, const float* __restrict__ W1, int N) {
    __shared__ float sW[F_IN * C1];
    for (int j = threadIdx.x; j < F_IN * C1; j += blockDim.x) sW[j] = W1[j];
    __syncthreads();
    int i = blockIdx.x * blockDim.x + threadIdx.x;
    if (i >= N) return;
    float dis = rsqrtf(g_dis[i]);
    g_dis[i] = dis;
    float xv[F_IN];
    #pragma unroll
    for (int d = 0; d < F_IN; d++) xv[d] = x[i * F_IN + d];
    #pragma unroll
    for (int f = 0; f < C1; f++) {
        float a = 0.f;
        #pragma unroll
        for (int d = 0; d < F_IN; d++) a = fmaf(xv[d], sW[d * C1 + f], a);
        float v = dis * a;
        g_hn [i * C1 + f] = v;
        g_acc[i * C1 + f] = v;
    }
}

// acc[col] += hn[row] per edge, one thread per (edge, feature)
__global__ void k_agg(const int* __restrict__ row, const int* __restrict__ col, int E) {
    int t = blockIdx.x * blockDim.x + threadIdx.x;
    int e = t >> 5;
    int f = t & 31;
    if (e >= E) return;
    atomicAdd(&g_acc[col[e] * C1 + f], g_hn[row[e] * C1 + f]);
}

// h1 = relu(dis*acc + b1); s = softmax(h1 @ pW1 + pb1); h1 stored back into g_hn
__global__ void k_s(const float* __restrict__ pW1, const float* __restrict__ pb1,
                    const float* __restrict__ b1, int N) {
    __shared__ float sW[C1 * K1];
    __shared__ float sb[K1];
    __shared__ float sb1[C1];
    for (int j = threadIdx.x; j < C1 * K1; j += blockDim.x) sW[j] = pW1[j];
    if (threadIdx.x < K1) sb[threadIdx.x]  = pb1[threadIdx.x];
    if (threadIdx.x < C1) sb1[threadIdx.x] = b1[threadIdx.x];
    __syncthreads();
    int i = blockIdx.x * blockDim.x + threadIdx.x;
    if (i >= N) return;
    float dis = g_dis[i];
    float h[C1];
    #pragma unroll
    for (int f = 0; f < C1; f++) {
        float v = fmaxf(fmaf(dis, g_acc[i * C1 + f], sb1[f]), 0.f);
        h[f] = v;
        g_hn[i * C1 + f] = v;
    }
    float logit[K1];
    float mx = -1e30f;
    #pragma unroll
    for (int k = 0; k < K1; k++) {
        float a = sb[k];
        #pragma unroll
        for (int f = 0; f < C1; f++) a = fmaf(h[f], sW[f * K1 + k], a);
        logit[k] = a;
        mx = fmaxf(mx, a);
    }
    float ssum = 0.f;
    #pragma unroll
    for (int k = 0; k < K1; k++) { float e = expf(logit[k] - mx); logit[k] = e; ssum += e; }
    float inv = 1.f / ssum;
    #pragma unroll
    for (int k = 0; k < K1; k++) g_s[i * K1 + k] = logit[k] * inv;
}

// a_s[row] += s[col] per edge (adj @ s; adj[e0][e1] += 1)
__global__ void k_as(const int* __restrict__ row, const int* __restrict__ col, int E) {
    int t = blockIdx.x * blockDim.x + threadIdx.x;
    int e = t / K1;
    int k = t - e * K1;
    if (e >= E) return;
    atomicAdd(&g_as[row[e] * K1 + k], g_s[col[e] * K1 + k]);
}

// out1[k,f] = sum_n s[n,k]*h1[n,f] ; adj1[k,l] = sum_n s[n,k]*as[n,l]
__global__ void k_red(int N) {
    int k     = blockIdx.x;   // 0..K1-1
    int chunk = blockIdx.y;
    int tid   = threadIdx.x;
    int per = (N + gridDim.y - 1) / gridDim.y;
    int n0 = chunk * per;
    int n1 = min(n0 + per, N);
    if (tid < 32) {
        int f = tid;
        float a0 = 0.f, a1 = 0.f;
        int n = n0;
        for (; n + 1 < n1; n += 2) {
            a0 = fmaf(g_s[n * K1 + k],       g_hn[n * C1 + f],       a0);
            a1 = fmaf(g_s[(n + 1) * K1 + k], g_hn[(n + 1) * C1 + f], a1);
        }
        if (n < n1) a0 = fmaf(g_s[n * K1 + k], g_hn[n * C1 + f], a0);
        atomicAdd(&g_out1[k * C1 + f], a0 + a1);
    } else if (tid < 32 + K1) {
        int l = tid - 32;
        float a0 = 0.f, a1 = 0.f;
        int n = n0;
        for (; n + 1 < n1; n += 2) {
            a0 = fmaf(g_s[n * K1 + k],       g_as[n * K1 + l],       a0);
            a1 = fmaf(g_s[(n + 1) * K1 + k], g_as[(n + 1) * K1 + l], a1);
        }
        if (n < n1) a0 = fmaf(g_s[n * K1 + k], g_as[n * K1 + l], a0);
        atomicAdd(&g_adj1[k * K1 + l], a0 + a1);
    }
}

// Everything after the first pool: tiny, single block.
__global__ void k_final(const float* __restrict__ W2,  const float* __restrict__ b2,
                        const float* __restrict__ pW2, const float* __restrict__ pb2,
                        const float* __restrict__ W3,  const float* __restrict__ b3,
                        const float* __restrict__ l1W, const float* __restrict__ l1b,
                        const float* __restrict__ l2W, const float* __restrict__ l2b,
                        float* __restrict__ out) {
    __shared__ float sh_adj [K1 * K1];   // normalized pool-1 adjacency (diag 0)
    __shared__ float sh_adjn[K1 * K1];
    __shared__ float sh_t   [K1 * C1];
    __shared__ float sh_x2  [K1 * C1];
    __shared__ float sh_s2  [K1 * K2];
    __shared__ float sh_as2 [K1 * K2];
    __shared__ float sh_out2[K2 * C1];
    __shared__ float sh_adj2[K2 * K2];
    __shared__ float sh_adj2n[K2 * K2];
    __shared__ float sh_t3  [K2 * C1];
    __shared__ float sh_x3  [K2 * C1];
    __shared__ float sh_d   [K1];
    __shared__ float sh_deg [K1];
    __shared__ float sh_g   [64];
    __shared__ float sh_fc  [32];
    const int tid = threadIdx.x;
    const int NT  = blockDim.x;

    // ---- pool-1 adjacency normalization: diag 0, d = sqrt(rowsum)+eps ----
    if (tid < K1) {
        float s = 0.f;
        for (int l = 0; l < K1; l++) if (l != tid) s += g_adj1[tid * K1 + l];
        sh_d[tid] = sqrtf(s) + EPSF;
    }
    __syncthreads();
    for (int i = tid; i < K1 * K1; i += NT) {
        int k = i / K1, l = i - k * K1;
        sh_adj[i] = (k == l) ? 0.f : g_adj1[i] / (sh_d[k] * sh_d[l]);
    }
    __syncthreads();

    // ---- DenseGCNConv(W2): diag=1, deg=max(sum,1)^-1/2, relu ----
    if (tid < K1) {
        float s = 1.f;
        for (int l = 0; l < K1; l++) s += sh_adj[tid * K1 + l];
        sh_deg[tid] = rsqrtf(fmaxf(s, 1.f));
    }
    __syncthreads();
    for (int i = tid; i < K1 * K1; i += NT) {
        int k = i / K1, l = i - k * K1;
        float a = sh_adj[i] + ((k == l) ? 1.f : 0.f);
        sh_adjn[i] = a * sh_deg[k] * sh_deg[l];
    }
    for (int i = tid; i < K1 * C1; i += NT) {
        int n = i / C1, f = i - n * C1;
        float a = 0.f;
        for (int c = 0; c < C1; c++) a = fmaf(g_out1[n * C1 + c], W2[c * C1 + f], a);
        sh_t[i] = a;
    }
    __syncthreads();
    for (int i = tid; i < K1 * C1; i += NT) {
        int n = i / C1, f = i - n * C1;
        float a = b2[f];
        for (int m = 0; m < K1; m++) a = fmaf(sh_adjn[n * K1 + m], sh_t[m * C1 + f], a);
        sh_x2[i] = fmaxf(a, 0.f);
    }
    __syncthreads();

    // ---- s2 = softmax(x2 @ pW2 + pb2) ----
    if (tid < K1) {
        float logit[K2];
        float mx = -1e30f;
        for (int k = 0; k < K2; k++) {
            float a = pb2[k];
            for (int f = 0; f < C1; f++) a = fmaf(sh_x2[tid * C1 + f], pW2[f * K2 + k], a);
            logit[k] = a;
            mx = fmaxf(mx, a);
        }
        float ssum = 0.f;
        for (int k = 0; k < K2; k++) { float e = expf(logit[k] - mx); logit[k] = e; ssum += e; }
        float inv = 1.f / ssum;
        for (int k = 0; k < K2; k++) sh_s2[tid * K2 + k] = logit[k] * inv;
    }
    __syncthreads();

    // ---- pool 2 ----
    for (int i = tid; i < K2 * C1; i += NT) {
        int k = i / C1, f = i - k * C1;
        float a = 0.f;
        for (int n = 0; n < K1; n++) a = fmaf(sh_s2[n * K2 + k], sh_x2[n * C1 + f], a);
        sh_out2[i] = a;
    }
    for (int i = tid; i < K1 * K2; i += NT) {
        int n = i / K2, l = i - n * K2;
        float a = 0.f;
        for (int m = 0; m < K1; m++) a = fmaf(sh_adj[n * K1 + m], sh_s2[m * K2 + l], a);
        sh_as2[i] = a;
    }
    __syncthreads();
    for (int i = tid; i < K2 * K2; i += NT) {
        int k = i / K2, l = i - k * K2;
        float a = 0.f;
        for (int n = 0; n < K1; n++) a = fmaf(sh_s2[n * K2 + k], sh_as2[n * K2 + l], a);
        sh_adj2[i] = (k == l) ? 0.f : a;
    }
    __syncthreads();
    if (tid < K2) {
        float s = 0.f;
        for (int l = 0; l < K2; l++) s += sh_adj2[tid * K2 + l];
        sh_d[tid] = sqrtf(s) + EPSF;
    }
    __syncthreads();
    for (int i = tid; i < K2 * K2; i += NT) {
        int k = i / K2, l = i - k * K2;
        sh_adj2[i] = sh_adj2[i] / (sh_d[k] * sh_d[l]);
    }
    __syncthreads();

    // ---- DenseGCNConv(W3), no relu ----
    if (tid < K2) {
        float s = 1.f;
        for (int l = 0; l < K2; l++) s += sh_adj2[tid * K2 + l];
        sh_deg[tid] = rsqrtf(fmaxf(s, 1.f));
    }
    __syncthreads();
    for (int i = tid; i < K2 * K2; i += NT) {
        int k = i / K2, l = i - k * K2;
        float a = sh_adj2[i] + ((k == l) ? 1.f : 0.f);
        sh_adj2n[i] = a * sh_deg[k] * sh_deg[l];
    }
    for (int i = tid; i < K2 * C1; i += NT) {
        int n = i / C1, f = i - n * C1;
        float a = 0.f;
        for (int c = 0; c < C1; c++) a = fmaf(sh_out2[n * C1 + c], W3[c * C1 + f], a);
        sh_t3[i] = a;
    }
    __syncthreads();
    for (int i = tid; i < K2 * C1; i += NT) {
        int n = i / C1, f = i - n * C1;
        float a = b3[f];
        for (int m = 0; m < K2; m++) a = fmaf(sh_adj2n[n * K2 + m], sh_t3[m * C1 + f], a);
        sh_x3[i] = a;
    }
    __syncthreads();

    // ---- readout + MLP ----
    if (tid < C1) {
        float s = 0.f;
        for (int n = 0; n < K2; n++) s += sh_x3[n * C1 + tid];
        sh_g[tid]      = s / (float)K2;   // mean
        sh_g[32 + tid] = s;               // sum
    }
    __syncthreads();
    if (tid < 32) {
        float a = l1b[tid];
        for (int i = 0; i < 64; i++) a = fmaf(sh_g[i], l1W[i * 32 + tid], a);
        sh_fc[tid] = fmaxf(a, 0.f);
    }
    __syncthreads();
    if (tid < 2) {
        float a = l2b[tid];
        for (int j = 0; j < 32; j++) a = fmaf(sh_fc[j], l2W[j * 2 + tid], a);
        out[tid] = a;
    }
}

// ---------------- launch ------------------------------------------------------
extern "C" void kernel_launch(void* const* d_in, const int* in_sizes, int n_in,
                              void* d_out, int out_size) {
    const float* x   = (const float*)d_in[0];
    const int*   ei  = (const int*)  d_in[1];
    const float* W1  = (const float*)d_in[2];
    const float* b1  = (const float*)d_in[3];
    const float* pW1 = (const float*)d_in[4];
    const float* pb1 = (const float*)d_in[5];
    const float* W2  = (const float*)d_in[6];
    const float* b2  = (const float*)d_in[7];
    const float* pW2 = (const float*)d_in[8];
    const float* pb2 = (const float*)d_in[9];
    const float* W3  = (const float*)d_in[10];
    const float* b3  = (const float*)d_in[11];
    const float* l1W = (const float*)d_in[12];
    const float* l1b = (const float*)d_in[13];
    const float* l2W = (const float*)d_in[14];
    const float* l2b = (const float*)d_in[15];
    float* out = (float*)d_out;

    const int N = in_sizes[0] / F_IN;     // 12000
    const int E = in_sizes[1] / 2;        // 192000
    const int* erow = ei;                 // edge_index[0] (sources)
    const int* ecol = ei + E;             // edge_index[1] (targets)

    k_init<<<(N * K1 + 255) / 256, 256>>>(N);
    k_deg <<<(E + 255) / 256, 256>>>(ecol, E);
    k_h   <<<(N + 127) / 128, 128>>>(x, W1, N);
    k_agg <<<(E * 32 + 255) / 256, 256>>>(erow, ecol, E);
    k_s   <<<(N + 127) / 128, 128>>>(pW1, pb1, b1, N);
    k_as  <<<(E * K1 + 255) / 256, 256>>>(erow, ecol, E);
    k_red <<<dim3(K1, RED_CHUNKS), 96>>>(N);
    k_final<<<1, 256>>>(W2, b2, pW2, pb2, W3, b3, l1W, l1b, l2W, l2b, out);
}

// round 2
// speedup vs baseline: 1.4890x; 1.4890x over previous
#include <cuda_runtime.h>
#include <math.h>

#define NMAX   12000
#define F_IN   10
#define C1     32
#define K1     35
#define K1P    36          // padded stride for s / as (144B, 16B-aligned)
#define K2     18
#define EPSF   1e-15f
#define RED_BLOCKS 100

// ---------------- device scratch (static: no runtime allocation) -------------
__device__ __align__(16) float g_dis[NMAX];          // degree, then D^-1/2
__device__ __align__(16) float g_hn [NMAX * C1];     // dis*(xW1), then h1
__device__ __align__(16) float g_acc[NMAX * C1];     // aggregation accumulator
__device__ __align__(16) float g_s  [NMAX * K1P];    // softmax assignments (padded)
__device__ __align__(16) float g_as [NMAX * K1P];    // adj @ s (padded)
__device__ __align__(16) float g_out1[K1 * C1];      // s^T h1
__device__ __align__(16) float g_adj1[K1 * K1P];     // s^T a_s (padded stride)

__device__ __forceinline__ void red4(float* p, float4 v) {
    asm volatile("red.global.add.v4.f32 [%0], {%1,%2,%3,%4};"
                 :: "l"(p), "f"(v.x), "f"(v.y), "f"(v.z), "f"(v.w) : "memory");
}

// ---------------- kernels ----------------------------------------------------

__global__ void k_init(int N) {
    int stride = gridDim.x * blockDim.x;
    int t0 = blockIdx.x * blockDim.x + threadIdx.x;
    for (int i = t0; i < N * K1P;  i += stride) g_as[i] = 0.f;
    for (int i = t0; i < N;        i += stride) g_dis[i] = 1.0f;   // self-loop
    for (int i = t0; i < K1*C1;    i += stride) g_out1[i] = 0.f;
    for (int i = t0; i < K1*K1P;   i += stride) g_adj1[i] = 0.f;
}

__global__ void k_deg(const int* __restrict__ col, int E) {
    int e = blockIdx.x * blockDim.x + threadIdx.x;
    if (e < E) atomicAdd(&g_dis[col[e]], 1.0f);
}

// dis = deg^-1/2 ; h = x @ W1 ; hn = dis*h ; acc starts as hn (self-loop term)
__global__ void k_h(const float* __restrict__ x, const float* __restrict__ W1, int N) {
    __shared__ float sW[F_IN * C1];
    for (int j = threadIdx.x; j < F_IN * C1; j += blockDim.x) sW[j] = W1[j];
    __syncthreads();
    int i = blockIdx.x * blockDim.x + threadIdx.x;
    if (i >= N) return;
    float dis = rsqrtf(g_dis[i]);
    g_dis[i] = dis;
    float xv[F_IN];
    #pragma unroll
    for (int d = 0; d < F_IN; d++) xv[d] = x[i * F_IN + d];
    #pragma unroll
    for (int f = 0; f < C1; f++) {
        float a = 0.f;
        #pragma unroll
        for (int d = 0; d < F_IN; d++) a = fmaf(xv[d], sW[d * C1 + f], a);
        float v = dis * a;
        g_hn [i * C1 + f] = v;
        g_acc[i * C1 + f] = v;
    }
}

// acc[col] += hn[row] per edge: 8 threads/edge, one float4 + one red.v4 each
__global__ void k_agg(const int* __restrict__ row, const int* __restrict__ col, int E) {
    int t = blockIdx.x * blockDim.x + threadIdx.x;
    int e = t >> 3;
    int q = (t & 7) << 2;
    if (e >= E) return;
    int r = __ldg(&row[e]);
    int c = __ldg(&col[e]);
    float4 v = *(const float4*)&g_hn[r * C1 + q];
    red4(&g_acc[c * C1 + q], v);
}

// h1 = relu(dis*acc + b1); s = softmax(h1 @ pW1 + pb1); h1 back into g_hn
__global__ void k_s(const float* __restrict__ pW1, const float* __restrict__ pb1,
                    const float* __restrict__ b1, int N) {
    __shared__ float sW[C1 * K1];
    __shared__ float sb[K1];
    __shared__ float sb1[C1];
    for (int j = threadIdx.x; j < C1 * K1; j += blockDim.x) sW[j] = pW1[j];
    if (threadIdx.x < K1) sb[threadIdx.x]  = pb1[threadIdx.x];
    if (threadIdx.x < C1) sb1[threadIdx.x] = b1[threadIdx.x];
    __syncthreads();
    int i = blockIdx.x * blockDim.x + threadIdx.x;
    if (i >= N) return;
    float dis = g_dis[i];
    float h[C1];
    #pragma unroll
    for (int f = 0; f < C1; f++) {
        float v = fmaxf(fmaf(dis, g_acc[i * C1 + f], sb1[f]), 0.f);
        h[f] = v;
        g_hn[i * C1 + f] = v;
    }
    float logit[K1];
    float mx = -1e30f;
    #pragma unroll
    for (int k = 0; k < K1; k++) {
        float a = sb[k];
        #pragma unroll
        for (int f = 0; f < C1; f++) a = fmaf(h[f], sW[f * K1 + k], a);
        logit[k] = a;
        mx = fmaxf(mx, a);
    }
    float ssum = 0.f;
    #pragma unroll
    for (int k = 0; k < K1; k++) { float e = expf(logit[k] - mx); logit[k] = e; ssum += e; }
    float inv = 1.f / ssum;
    #pragma unroll
    for (int k = 0; k < K1; k++) g_s[i * K1P + k] = logit[k] * inv;
    g_s[i * K1P + K1] = 0.f;   // pad column
}

// a_s[row] += s[col] per edge: 9 threads/edge (36 padded cols / 4)
__global__ void k_as(const int* __restrict__ row, const int* __restrict__ col, int E) {
    int t = blockIdx.x * blockDim.x + threadIdx.x;
    int e = t / 9;
    int q = (t - e * 9) << 2;
    if (e >= E) return;
    int r = __ldg(&row[e]);
    int c = __ldg(&col[e]);
    float4 v = *(const float4*)&g_s[c * K1P + q];
    red4(&g_as[r * K1P + q], v);
}

// out1[k,:] = sum_n s[n,k]*h1[n,:] ; adj1[k,:] = sum_n s[n,k]*as[n,:]
// 595 live threads = 35 k  x  17 float4 groups over V = [h1(32) | as(36)]
__global__ void k_red(int N) {
    const int tid = threadIdx.x;
    const int k  = tid / 17;
    const int jg = tid - k * 17;
    const bool live = (tid < K1 * 17);
    int per = (N + gridDim.x - 1) / gridDim.x;
    int n0 = blockIdx.x * per;
    int n1 = min(n0 + per, N);
    float4 acc = make_float4(0.f, 0.f, 0.f, 0.f);
    if (live) {
        const bool is_h = (jg < 8);
        const int off = is_h ? (jg << 2) : ((jg - 8) << 2);
        for (int n = n0; n < n1; n++) {
            float sv = __ldg(&g_s[n * K1P + k]);
            float4 v = is_h ? *(const float4*)&g_hn[n * C1  + off]
                            : *(const float4*)&g_as[n * K1P + off];
            acc.x = fmaf(sv, v.x, acc.x);
            acc.y = fmaf(sv, v.y, acc.y);
            acc.z = fmaf(sv, v.z, acc.z);
            acc.w = fmaf(sv, v.w, acc.w);
        }
        if (is_h) red4(&g_out1[k * C1 + off], acc);
        else      red4(&g_adj1[k * K1P + off], acc);
    }
}

// Everything after the first pool: tiny, single block.
__global__ void k_final(const float* __restrict__ W2,  const float* __restrict__ b2,
                        const float* __restrict__ pW2, const float* __restrict__ pb2,
                        const float* __restrict__ W3,  const float* __restrict__ b3,
                        const float* __restrict__ l1W, const float* __restrict__ l1b,
                        const float* __restrict__ l2W, const float* __restrict__ l2b,
                        float* __restrict__ out) {
    __shared__ float sh_adj [K1 * K1];
    __shared__ float sh_adjn[K1 * K1];
    __shared__ float sh_t   [K1 * C1];
    __shared__ float sh_x2  [K1 * C1];
    __shared__ float sh_s2  [K1 * K2];
    __shared__ float sh_as2 [K1 * K2];
    __shared__ float sh_out2[K2 * C1];
    __shared__ float sh_adj2[K2 * K2];
    __shared__ float sh_adj2n[K2 * K2];
    __shared__ float sh_t3  [K2 * C1];
    __shared__ float sh_x3  [K2 * C1];
    __shared__ float sh_d   [K1];
    __shared__ float sh_deg [K1];
    __shared__ float sh_g   [64];
    __shared__ float sh_fc  [32];
    const int tid = threadIdx.x;
    const int NT  = blockDim.x;

    // ---- pool-1 adjacency normalization: diag 0, d = sqrt(rowsum)+eps ----
    if (tid < K1) {
        float s = 0.f;
        for (int l = 0; l < K1; l++) if (l != tid) s += g_adj1[tid * K1P + l];
        sh_d[tid] = sqrtf(s) + EPSF;
    }
    __syncthreads();
    for (int i = tid; i < K1 * K1; i += NT) {
        int k = i / K1, l = i - k * K1;
        sh_adj[i] = (k == l) ? 0.f : g_adj1[k * K1P + l] / (sh_d[k] * sh_d[l]);
    }
    __syncthreads();

    // ---- DenseGCNConv(W2): diag=1, deg=max(sum,1)^-1/2, relu ----
    if (tid < K1) {
        float s = 1.f;
        for (int l = 0; l < K1; l++) s += sh_adj[tid * K1 + l];
        sh_deg[tid] = rsqrtf(fmaxf(s, 1.f));
    }
    __syncthreads();
    for (int i = tid; i < K1 * K1; i += NT) {
        int k = i / K1, l = i - k * K1;
        float a = sh_adj[i] + ((k == l) ? 1.f : 0.f);
        sh_adjn[i] = a * sh_deg[k] * sh_deg[l];
    }
    for (int i = tid; i < K1 * C1; i += NT) {
        int n = i / C1, f = i - n * C1;
        float a = 0.f;
        for (int c = 0; c < C1; c++) a = fmaf(g_out1[n * C1 + c], W2[c * C1 + f], a);
        sh_t[i] = a;
    }
    __syncthreads();
    for (int i = tid; i < K1 * C1; i += NT) {
        int n = i / C1, f = i - n * C1;
        float a = b2[f];
        for (int m = 0; m < K1; m++) a = fmaf(sh_adjn[n * K1 + m], sh_t[m * C1 + f], a);
        sh_x2[i] = fmaxf(a, 0.f);
    }
    __syncthreads();

    // ---- s2 = softmax(x2 @ pW2 + pb2) ----
    if (tid < K1) {
        float logit[K2];
        float mx = -1e30f;
        for (int k = 0; k < K2; k++) {
            float a = pb2[k];
            for (int f = 0; f < C1; f++) a = fmaf(sh_x2[tid * C1 + f], pW2[f * K2 + k], a);
            logit[k] = a;
            mx = fmaxf(mx, a);
        }
        float ssum = 0.f;
        for (int k = 0; k < K2; k++) { float e = expf(logit[k] - mx); logit[k] = e; ssum += e; }
        float inv = 1.f / ssum;
        for (int k = 0; k < K2; k++) sh_s2[tid * K2 + k] = logit[k] * inv;
    }
    __syncthreads();

    // ---- pool 2 ----
    for (int i = tid; i < K2 * C1; i += NT) {
        int k = i / C1, f = i - k * C1;
        float a = 0.f;
        for (int n = 0; n < K1; n++) a = fmaf(sh_s2[n * K2 + k], sh_x2[n * C1 + f], a);
        sh_out2[i] = a;
    }
    for (int i = tid; i < K1 * K2; i += NT) {
        int n = i / K2, l = i - n * K2;
        float a = 0.f;
        for (int m = 0; m < K1; m++) a = fmaf(sh_adj[n * K1 + m], sh_s2[m * K2 + l], a);
        sh_as2[i] = a;
    }
    __syncthreads();
    for (int i = tid; i < K2 * K2; i += NT) {
        int k = i / K2, l = i - k * K2;
        float a = 0.f;
        for (int n = 0; n < K1; n++) a = fmaf(sh_s2[n * K2 + k], sh_as2[n * K2 + l], a);
        sh_adj2[i] = (k == l) ? 0.f : a;
    }
    __syncthreads();
    if (tid < K2) {
        float s = 0.f;
        for (int l = 0; l < K2; l++) s += sh_adj2[tid * K2 + l];
        sh_d[tid] = sqrtf(s) + EPSF;
    }
    __syncthreads();
    for (int i = tid; i < K2 * K2; i += NT) {
        int k = i / K2, l = i - k * K2;
        sh_adj2[i] = sh_adj2[i] / (sh_d[k] * sh_d[l]);
    }
    __syncthreads();

    // ---- DenseGCNConv(W3), no relu ----
    if (tid < K2) {
        float s = 1.f;
        for (int l = 0; l < K2; l++) s += sh_adj2[tid * K2 + l];
        sh_deg[tid] = rsqrtf(fmaxf(s, 1.f));
    }
    __syncthreads();
    for (int i = tid; i < K2 * K2; i += NT) {
        int k = i / K2, l = i - k * K2;
        float a = sh_adj2[i] + ((k == l) ? 1.f : 0.f);
        sh_adj2n[i] = a * sh_deg[k] * sh_deg[l];
    }
    for (int i = tid; i < K2 * C1; i += NT) {
        int n = i / C1, f = i - n * C1;
        float a = 0.f;
        for (int c = 0; c < C1; c++) a = fmaf(sh_out2[n * C1 + c], W3[c * C1 + f], a);
        sh_t3[i] = a;
    }
    __syncthreads();
    for (int i = tid; i < K2 * C1; i += NT) {
        int n = i / C1, f = i - n * C1;
        float a = b3[f];
        for (int m = 0; m < K2; m++) a = fmaf(sh_adj2n[n * K2 + m], sh_t3[m * C1 + f], a);
        sh_x3[i] = a;
    }
    __syncthreads();

    // ---- readout + MLP ----
    if (tid < C1) {
        float s = 0.f;
        for (int n = 0; n < K2; n++) s += sh_x3[n * C1 + tid];
        sh_g[tid]      = s / (float)K2;   // mean
        sh_g[32 + tid] = s;               // sum
    }
    __syncthreads();
    if (tid < 32) {
        float a = l1b[tid];
        for (int i = 0; i < 64; i++) a = fmaf(sh_g[i], l1W[i * 32 + tid], a);
        sh_fc[tid] = fmaxf(a, 0.f);
    }
    __syncthreads();
    if (tid < 2) {
        float a = l2b[tid];
        for (int j = 0; j < 32; j++) a = fmaf(sh_fc[j], l2W[j * 2 + tid], a);
        out[tid] = a;
    }
}

// ---------------- launch ------------------------------------------------------
extern "C" void kernel_launch(void* const* d_in, const int* in_sizes, int n_in,
                              void* d_out, int out_size) {
    const float* x   = (const float*)d_in[0];
    const int*   ei  = (const int*)  d_in[1];
    const float* W1  = (const float*)d_in[2];
    const float* b1  = (const float*)d_in[3];
    const float* pW1 = (const float*)d_in[4];
    const float* pb1 = (const float*)d_in[5];
    const float* W2  = (const float*)d_in[6];
    const float* b2  = (const float*)d_in[7];
    const float* pW2 = (const float*)d_in[8];
    const float* pb2 = (const float*)d_in[9];
    const float* W3  = (const float*)d_in[10];
    const float* b3  = (const float*)d_in[11];
    const float* l1W = (const float*)d_in[12];
    const float* l1b = (const float*)d_in[13];
    const float* l2W = (const float*)d_in[14];
    const float* l2b = (const float*)d_in[15];
    float* out = (float*)d_out;

    const int N = in_sizes[0] / F_IN;     // 12000
    const int E = in_sizes[1] / 2;        // 192000
    const int* erow = ei;                 // edge_index[0] (sources)
    const int* ecol = ei + E;             // edge_index[1] (targets)

    k_init<<<(N * K1P + 255) / 256, 256>>>(N);
    k_deg <<<(E + 255) / 256, 256>>>(ecol, E);
    k_h   <<<(N + 127) / 128, 128>>>(x, W1, N);
    k_agg <<<(E * 8 + 255) / 256, 256>>>(erow, ecol, E);
    k_s   <<<(N + 127) / 128, 128>>>(pW1, pb1, b1, N);
    k_as  <<<(E * 9 + 255) / 256, 256>>>(erow, ecol, E);
    k_red <<<RED_BLOCKS, 608>>>(N);
    k_final<<<1, 256>>>(W2, b2, pW2, pb2, W3, b3, l1W, l1b, l2W, l2b, out);
}